// round 3
// baseline (speedup 1.0000x reference)
#include <cuda_runtime.h>
#include <cuda_bf16.h>

// SmallVDSR: 20-layer 3x3 conv stack on [8,1,512,512] fp32.
//   conv1: 1->8 + relu        (scalar kernel)
//   conv2..19: 18x (8->8+relu) (packed f32x2 kernel, oc-pairs)
//   conv20: 8->1, no relu     (scalar kernel)

#define H 512
#define W 512
#define NB 8
#define PLANE (H * W)

typedef unsigned long long u64;

__device__ float g_bufA[NB * 8 * PLANE];
__device__ float g_bufB[NB * 8 * PLANE];

__device__ __forceinline__ u64 pack_dup(float v) {
    u64 r;
    asm("mov.b64 %0, {%1, %1};" : "=l"(r) : "f"(v));
    return r;
}
__device__ __forceinline__ void fma2(u64& acc, u64 a, u64 b) {
    asm("fma.rn.f32x2 %0, %1, %2, %0;" : "+l"(acc) : "l"(a), "l"(b));
}
__device__ __forceinline__ void unpack2(float& lo, float& hi, u64 v) {
    asm("mov.b64 {%0, %1}, %2;" : "=f"(lo), "=f"(hi) : "l"(v));
}
__device__ __forceinline__ u64 pack2(float lo, float hi) {
    u64 r;
    asm("mov.b64 %0, {%1, %2};" : "=l"(r) : "f"(lo), "f"(hi));
    return r;
}

// ---------------------------------------------------------------------------
// Mid layers: IC=8 -> OC=8, relu. Packed f32x2 over oc-pairs.
// Block = (32,8), 32x32 output tile, RY=4 rows/thread, all 8 oc per thread.
// ---------------------------------------------------------------------------
__global__ void __launch_bounds__(256, 2)
conv3x3_88_kernel(const float* __restrict__ in,
                  const float* __restrict__ wg,
                  float* __restrict__ out)
{
    constexpr int TX = 32, TY = 32, RY = 4;
    constexpr int SW = TX + 2;            // 34
    constexpr int STILE = SW * (TY + 2);  // 1156

    __shared__ float s_in[8 * STILE];
    __shared__ u64   s_w[8 * 9 * 4];      // [ic][k][p], p = oc-pair (oc=2p,2p+1)

    const int tx  = threadIdx.x;
    const int ty  = threadIdx.y;
    const int tid = ty * 32 + tx;
    const int n   = blockIdx.z;
    const int gx0 = blockIdx.x * TX;
    const int gy0 = blockIdx.y * TY;

    const float* inb = in + (size_t)n * 8 * PLANE;

    // ---- stage input tile (1-pixel zero halo) ----
    #pragma unroll 1
    for (int idx = tid; idx < 8 * STILE; idx += 256) {
        int ic = idx / STILE;
        int r  = idx - ic * STILE;
        int sy = r / SW;
        int sx = r - sy * SW;
        int gy = gy0 + sy - 1;
        int gx = gx0 + sx - 1;
        float v = 0.0f;
        if (gy >= 0 && gy < H && gx >= 0 && gx < W)
            v = inb[ic * PLANE + (gy << 9) + gx];
        s_in[idx] = v;
    }

    // ---- stage + repack weights: global [oc][ic][k] -> smem [ic][k][p] (f32x2) ----
    #pragma unroll 1
    for (int idx = tid; idx < 8 * 9 * 4; idx += 256) {
        int p  = idx & 3;
        int t  = idx >> 2;
        int k  = t % 9;
        int ic = t / 9;
        float lo = wg[((2 * p + 0) * 8 + ic) * 9 + k];
        float hi = wg[((2 * p + 1) * 8 + ic) * 9 + k];
        s_w[idx] = pack2(lo, hi);
    }

    __syncthreads();

    u64 acc[RY][4];
    #pragma unroll
    for (int ry = 0; ry < RY; ++ry)
        #pragma unroll
        for (int p = 0; p < 4; ++p)
            acc[ry][p] = 0ull;

    const int y0 = ty * RY;

    #pragma unroll 1
    for (int ic = 0; ic < 8; ++ic) {
        const float* si  = &s_in[ic * STILE + y0 * SW + tx];
        const u64*   swp = &s_w[ic * 36];

        #pragma unroll
        for (int ky = 0; ky < 3; ++ky) {
            // weight block for this ky: 3 kx x 4 pairs (broadcast LDS.64)
            u64 w0[4], w1[4], w2[4];
            #pragma unroll
            for (int p = 0; p < 4; ++p) {
                w0[p] = swp[(ky * 3 + 0) * 4 + p];
                w1[p] = swp[(ky * 3 + 1) * 4 + p];
                w2[p] = swp[(ky * 3 + 2) * 4 + p];
            }
            #pragma unroll
            for (int ry = 0; ry < RY; ++ry) {
                const float* r = si + (ry + ky) * SW;
                u64 v0 = pack_dup(r[0]);
                u64 v1 = pack_dup(r[1]);
                u64 v2 = pack_dup(r[2]);
                #pragma unroll
                for (int p = 0; p < 4; ++p) {
                    fma2(acc[ry][p], v0, w0[p]);
                    fma2(acc[ry][p], v1, w1[p]);
                    fma2(acc[ry][p], v2, w2[p]);
                }
            }
        }
    }

    // ---- write out (relu) ----
    float* outb = out + (size_t)n * 8 * PLANE;
    #pragma unroll
    for (int ry = 0; ry < RY; ++ry) {
        int off = ((gy0 + y0 + ry) << 9) + gx0 + tx;
        #pragma unroll
        for (int p = 0; p < 4; ++p) {
            float lo, hi;
            unpack2(lo, hi, acc[ry][p]);
            outb[(2 * p + 0) * PLANE + off] = fmaxf(lo, 0.0f);
            outb[(2 * p + 1) * PLANE + off] = fmaxf(hi, 0.0f);
        }
    }
}

// ---------------------------------------------------------------------------
// Generic scalar kernel (used for conv1: 1->8 relu, conv20: 8->1 no relu)
// ---------------------------------------------------------------------------
template <int IC, int OC, bool RELU>
__global__ void __launch_bounds__(256, 4)
conv3x3_kernel(const float* __restrict__ in,
               const float* __restrict__ wg,
               float* __restrict__ out)
{
    constexpr int TX = 32, TY = 32, RY = 4;
    constexpr int SW = TX + 2;
    constexpr int STILE = SW * (TY + 2);

    __shared__ float s_in[IC * STILE];
    __shared__ float s_w[IC * 9 * OC];

    const int tx  = threadIdx.x;
    const int ty  = threadIdx.y;
    const int tid = ty * 32 + tx;
    const int n   = blockIdx.z;
    const int gx0 = blockIdx.x * TX;
    const int gy0 = blockIdx.y * TY;

    const float* inb = in + (size_t)n * IC * PLANE;

    #pragma unroll 1
    for (int idx = tid; idx < IC * STILE; idx += 256) {
        int ic = idx / STILE;
        int r  = idx - ic * STILE;
        int sy = r / SW;
        int sx = r - sy * SW;
        int gy = gy0 + sy - 1;
        int gx = gx0 + sx - 1;
        float v = 0.0f;
        if (gy >= 0 && gy < H && gx >= 0 && gx < W)
            v = inb[ic * PLANE + (gy << 9) + gx];
        s_in[idx] = v;
    }

    #pragma unroll 1
    for (int idx = tid; idx < IC * 9 * OC; idx += 256) {
        int oc = idx % OC;
        int t  = idx / OC;
        int ic = t / 9;
        int k  = t - ic * 9;
        s_w[idx] = wg[(oc * IC + ic) * 9 + k];
    }

    __syncthreads();

    float acc[RY][OC];
    #pragma unroll
    for (int ry = 0; ry < RY; ++ry)
        #pragma unroll
        for (int oc = 0; oc < OC; ++oc)
            acc[ry][oc] = 0.0f;

    const int y0 = ty * RY;

    #pragma unroll 1
    for (int ic = 0; ic < IC; ++ic) {
        const float* si = &s_in[ic * STILE];
        const float* sw = &s_w[ic * 9 * OC];
        #pragma unroll
        for (int ky = 0; ky < 3; ++ky) {
            #pragma unroll
            for (int kx = 0; kx < 3; ++kx) {
                float wv[OC];
                #pragma unroll
                for (int oc = 0; oc < OC; ++oc)
                    wv[oc] = sw[(ky * 3 + kx) * OC + oc];
                #pragma unroll
                for (int ry = 0; ry < RY; ++ry) {
                    float v = si[(y0 + ry + ky) * SW + tx + kx];
                    #pragma unroll
                    for (int oc = 0; oc < OC; ++oc)
                        acc[ry][oc] = fmaf(v, wv[oc], acc[ry][oc]);
                }
            }
        }
    }

    float* outb = out + (size_t)n * OC * PLANE;
    #pragma unroll
    for (int ry = 0; ry < RY; ++ry) {
        int gy = gy0 + y0 + ry;
        #pragma unroll
        for (int oc = 0; oc < OC; ++oc) {
            float v = acc[ry][oc];
            if (RELU) v = fmaxf(v, 0.0f);
            outb[oc * PLANE + (gy << 9) + gx0 + tx] = v;
        }
    }
}

extern "C" void kernel_launch(void* const* d_in, const int* in_sizes, int n_in,
                              void* d_out, int out_size)
{
    const float* x    = (const float*)d_in[0];  // [8,1,512,512]
    const float* w1   = (const float*)d_in[1];  // [8,1,3,3]
    const float* wmid = (const float*)d_in[2];  // [18,8,8,3,3]
    const float* w20  = (const float*)d_in[3];  // [1,8,3,3]
    float* out = (float*)d_out;                 // [8,1,512,512]

    float* bufA = nullptr;
    float* bufB = nullptr;
    cudaGetSymbolAddress((void**)&bufA, g_bufA);
    cudaGetSymbolAddress((void**)&bufB, g_bufB);

    dim3 block(32, 8);
    dim3 grid(W / 32, H / 32, NB);

    // conv1: 1 -> 8, relu (scalar)
    conv3x3_kernel<1, 8, true><<<grid, block>>>(x, w1, bufA);

    // conv2..19: 18x 8 -> 8, relu (packed f32x2)
    float* src = bufA;
    float* dst = bufB;
    for (int l = 0; l < 18; ++l) {
        conv3x3_88_kernel<<<grid, block>>>(src, wmid + (size_t)l * 8 * 8 * 9, dst);
        float* t = src; src = dst; dst = t;
    }

    // conv20: 8 -> 1, no relu (scalar)
    conv3x3_kernel<8, 1, false><<<grid, block>>>(src, w20, out);
}